// round 8
// baseline (speedup 1.0000x reference)
#include <cuda_runtime.h>
#include <cuda_bf16.h>
#include <math.h>
#include <stdint.h>

#define Bsz 64
#define Lsz 512
#define DIN 1024
#define Hsz 1024
#define Gsz 4096
#define ML (Bsz*Lsz)            // 32768
#define OUTN ((size_t)Bsz*Lsz*Hsz) // 33554432

// ---------------- scratch (static device allocations) ----------------
__device__ float g_xproj[(size_t)ML*Gsz];                 // 512 MB
__device__ __nv_bfloat16 g_xhi[(size_t)ML*DIN];
__device__ __nv_bfloat16 g_xlo[(size_t)ML*DIN];
__device__ __nv_bfloat16 g_wxhi[(size_t)Gsz*DIN];
__device__ __nv_bfloat16 g_wxlo[(size_t)Gsz*DIN];
__device__ __nv_bfloat16 g_whhi[(size_t)Gsz*Hsz];
__device__ __nv_bfloat16 g_whlo[(size_t)Gsz*Hsz];
__device__ __nv_bfloat16 g_hhi3[3][Bsz*Hsz];
__device__ __nv_bfloat16 g_hlo3[3][Bsz*Hsz];
__device__ unsigned g_rc[8];    // per-K-region step counters

// ---------------- helpers ----------------
__device__ __forceinline__ void mma16816(float* c, const unsigned* a, const unsigned* b) {
    asm volatile(
        "mma.sync.aligned.m16n8k16.row.col.f32.bf16.bf16.f32 "
        "{%0,%1,%2,%3}, {%4,%5,%6,%7}, {%8,%9}, {%0,%1,%2,%3};\n"
        : "+f"(c[0]), "+f"(c[1]), "+f"(c[2]), "+f"(c[3])
        : "r"(a[0]), "r"(a[1]), "r"(a[2]), "r"(a[3]), "r"(b[0]), "r"(b[1]));
}

__device__ __forceinline__ void ldsm_x4(unsigned* r, const void* p) {
    unsigned a = (unsigned)__cvta_generic_to_shared(p);
    asm volatile("ldmatrix.sync.aligned.m8n8.x4.shared.b16 {%0,%1,%2,%3}, [%4];\n"
        : "=r"(r[0]), "=r"(r[1]), "=r"(r[2]), "=r"(r[3]) : "r"(a));
}

__device__ __forceinline__ void cp16(void* dst, const void* src) {
    unsigned d = (unsigned)__cvta_generic_to_shared(dst);
    asm volatile("cp.async.cg.shared.global [%0], [%1], 16;\n" :: "r"(d), "l"(src));
}
__device__ __forceinline__ void cp_commit() { asm volatile("cp.async.commit_group;\n"); }
__device__ __forceinline__ void cp_wait1()  { asm volatile("cp.async.wait_group 1;\n"); }
__device__ __forceinline__ void cp_wait0()  { asm volatile("cp.async.wait_group 0;\n"); }

__device__ __forceinline__ unsigned ld_acq(const unsigned* p) {
    unsigned v;
    asm volatile("ld.acquire.gpu.global.u32 %0, [%1];" : "=r"(v) : "l"(p));
    return v;
}

__device__ __forceinline__ float sigmoidf_(float x) {
    return __fdividef(1.0f, 1.0f + __expf(-x));
}
__device__ __forceinline__ float tanhf_(float x) {
    return __fdividef(2.0f, 1.0f + __expf(-2.0f * x)) - 1.0f;
}

// ---------------- split kernels ----------------
__global__ void split_x_kernel(const float* __restrict__ x) {
    size_t stride = (size_t)gridDim.x * blockDim.x;
    for (size_t i = (size_t)blockIdx.x * blockDim.x + threadIdx.x;
         i < (size_t)ML * DIN; i += stride) {
        float v = x[i];
        __nv_bfloat16 hi = __float2bfloat16(v);
        g_xhi[i] = hi;
        g_xlo[i] = __float2bfloat16(v - __bfloat162float(hi));
    }
}

__global__ void split_w_kernel(const float* __restrict__ W) {
    size_t stride = (size_t)gridDim.x * blockDim.x;
    for (size_t i = (size_t)blockIdx.x * blockDim.x + threadIdx.x;
         i < (size_t)Gsz * (Hsz + DIN); i += stride) {
        int r = (int)(i >> 11);
        int c = (int)(i & 2047);
        float v = W[i];
        __nv_bfloat16 hi = __float2bfloat16(v);
        __nv_bfloat16 lo = __float2bfloat16(v - __bfloat162float(hi));
        size_t d = (size_t)r * 1024 + (c & 1023);
        if (c < 1024) { g_whhi[d] = hi; g_whlo[d] = lo; }
        else          { g_wxhi[d] = hi; g_wxlo[d] = lo; }
    }
}

__global__ void init_kernel() {
    int i = blockIdx.x * blockDim.x + threadIdx.x;
    if (i < 8) g_rc[i] = 0;
    if (i < Bsz * Hsz) {
        __nv_bfloat16 z = __float2bfloat16(0.0f);
        g_hhi3[0][i] = z;
        g_hlo3[0][i] = z;
    }
}

// ---------------- phase 1: x_proj GEMM (R6 verbatim: reg-capped, 2 CTA/SM) ----------------
#define P1_BM 128
#define P1_BN 128
#define P1_BK 32
#define P1_ROW 40   // 32 + 8 pad

__global__ __launch_bounds__(256, 2) void xproj_kernel(const float* __restrict__ bias) {
    __shared__ __nv_bfloat16 As[2][2][P1_BM][P1_ROW];  // [buf][hi/lo]
    __shared__ __nv_bfloat16 Bs[2][2][P1_BN][P1_ROW];

    const int tid = threadIdx.x;
    const int wid = tid >> 5, lane = tid & 31;
    const int wm = wid & 3;
    const int wn = wid >> 2;
    const int m0 = blockIdx.y * P1_BM;
    const int n0 = blockIdx.x * P1_BN;

    float acc[2][8][4];
    #pragma unroll
    for (int i = 0; i < 2; ++i)
        #pragma unroll
        for (int j = 0; j < 8; ++j)
            #pragma unroll
            for (int k = 0; k < 4; ++k) acc[i][j][k] = 0.0f;

    const int lrow = tid >> 1;
    const int lcb  = (tid & 1) * 16;

    const __nv_bfloat16* srcAh = g_xhi  + (size_t)(m0 + lrow) * DIN + lcb;
    const __nv_bfloat16* srcAl = g_xlo  + (size_t)(m0 + lrow) * DIN + lcb;
    const __nv_bfloat16* srcBh = g_wxhi + (size_t)(n0 + lrow) * DIN + lcb;
    const __nv_bfloat16* srcBl = g_wxlo + (size_t)(n0 + lrow) * DIN + lcb;

    auto stage = [&](int buf, int k0) {
        cp16(&As[buf][0][lrow][lcb],     srcAh + k0);
        cp16(&As[buf][0][lrow][lcb + 8], srcAh + k0 + 8);
        cp16(&As[buf][1][lrow][lcb],     srcAl + k0);
        cp16(&As[buf][1][lrow][lcb + 8], srcAl + k0 + 8);
        cp16(&Bs[buf][0][lrow][lcb],     srcBh + k0);
        cp16(&Bs[buf][0][lrow][lcb + 8], srcBh + k0 + 8);
        cp16(&Bs[buf][1][lrow][lcb],     srcBl + k0);
        cp16(&Bs[buf][1][lrow][lcb + 8], srcBl + k0 + 8);
        cp_commit();
    };

    stage(0, 0);

    const int aRow = lane & 15;
    const int aCol = (lane >> 4) << 3;
    const int bRow = ((lane >> 4) << 3) + (lane & 7);
    const int bCol = ((lane >> 3) & 1) << 3;

    for (int k0 = 0; k0 < DIN; k0 += P1_BK) {
        const int buf = (k0 >> 5) & 1;
        const bool more = (k0 + P1_BK) < DIN;
        if (more) stage(buf ^ 1, k0 + P1_BK);
        if (more) cp_wait1(); else cp_wait0();
        __syncthreads();

        #pragma unroll
        for (int kk = 0; kk < 2; ++kk) {
            const int kb = kk * 16;
            unsigned ahi[2][4], alo[2][4];
            #pragma unroll
            for (int mt = 0; mt < 2; ++mt) {
                const int r0 = wm * 32 + mt * 16;
                ldsm_x4(ahi[mt], &As[buf][0][r0 + aRow][kb + aCol]);
                ldsm_x4(alo[mt], &As[buf][1][r0 + aRow][kb + aCol]);
            }
            #pragma unroll
            for (int p = 0; p < 4; ++p) {
                const int nb0 = wn * 64 + p * 16;
                unsigned bh[4], bl[4];
                ldsm_x4(bh, &Bs[buf][0][nb0 + bRow][kb + bCol]);
                ldsm_x4(bl, &Bs[buf][1][nb0 + bRow][kb + bCol]);
                #pragma unroll
                for (int mt = 0; mt < 2; ++mt) {
                    #pragma unroll
                    for (int q = 0; q < 2; ++q) {
                        float* a = acc[mt][p * 2 + q];
                        mma16816(a, ahi[mt], bh + 2 * q);
                        mma16816(a, ahi[mt], bl + 2 * q);
                        mma16816(a, alo[mt], bh + 2 * q);
                    }
                }
            }
        }
        __syncthreads();
    }

    // epilogue: +bias, store fp32
    const int g = lane >> 2, tg = lane & 3;
    #pragma unroll
    for (int nt = 0; nt < 8; ++nt) {
        const int c = n0 + wn * 64 + nt * 8 + 2 * tg;
        const float bv0 = bias[c], bv1 = bias[c + 1];
        #pragma unroll
        for (int mt = 0; mt < 2; ++mt) {
            const int r0 = m0 + wm * 32 + mt * 16 + g;
            float2 v0 = make_float2(acc[mt][nt][0] + bv0, acc[mt][nt][1] + bv1);
            float2 v1 = make_float2(acc[mt][nt][2] + bv0, acc[mt][nt][3] + bv1);
            *(float2*)&g_xproj[(size_t)r0 * Gsz + c]       = v0;
            *(float2*)&g_xproj[(size_t)(r0 + 8) * Gsz + c] = v1;
        }
    }
}

// ---------------- phase 2: persistent recurrent LSTM ----------------
// 16 warps = 4 row-groups (m16) x 4 k-segments (k32/chunk). A fragments loaded
// directly from global h into registers (double-buffered by k-tile). B from
// persistent Wh SMEM via ldmatrix. NO __syncthreads in the k-loop; 4-way
// split-K reduced via SMEM once per step.
#define NBLK2 128
#define HPERB 8
#define NG 32
#define WPAD 8           // wh row length 1032
#define NTH2 512
#define NKT 16           // k-tiles of 16 per step (16*16*4seg? no: per warp 16 tiles x ... )

#define SM_WH   (NG * (Hsz + WPAD))
#define SMEM_P2 ((size_t)(2*SM_WH) * 2 + (size_t)(4*Bsz*NG) * 4)

__global__ __launch_bounds__(NTH2, 1) void lstm_kernel(float* __restrict__ out) {
    extern __shared__ char smem[];
    __nv_bfloat16* whhi = (__nv_bfloat16*)smem;               // [NG][1032]
    __nv_bfloat16* whlo = whhi + SM_WH;
    float* gates = (float*)(whlo + SM_WH);                     // [4][64][32] partials

    const int tid = threadIdx.x;
    const int wid = tid >> 5, lane = tid & 31;
    const int g = lane >> 2, tg = lane & 3;
    const int wm = wid & 3;              // batch rows wm*16
    const int kseg = wid >> 2;           // k-segment 0..3 (k32 within each 128-chunk)
    const int j0 = blockIdx.x * HPERB;
    const int region = blockIdx.x >> 4;

    // B ldmatrix lane-address components (rows 0-15 and 16-31 of NG)
    const int bR0 = ((lane >> 4) << 3) + (lane & 7);
    const int bR1 = 16 + bR0;
    const int bCol = ((lane >> 3) & 1) << 3;

    // A fragment rows for this thread
    const int row0 = wm * 16 + g;
    const int row1 = row0 + 8;

    // Wh slice into SMEM
    for (int i = tid; i < NG * (Hsz / 8); i += NTH2) {
        const int n = i >> 7;
        const int cu = i & 127;
        const int q = n >> 3, jj = n & 7;
        const size_t src = (size_t)(q * 1024 + j0 + jj) * Hsz + cu * 8;
        *(uint4*)&whhi[n * (Hsz + WPAD) + cu * 8] = *(const uint4*)(g_whhi + src);
        *(uint4*)&whlo[n * (Hsz + WPAD) + cu * 8] = *(const uint4*)(g_whlo + src);
    }
    __syncthreads();

    // cell item: one per thread
    const int b_0 = tid >> 3, jj_0 = tid & 7;
    float c_reg = 0.0f;

    // prefetch xproj for step 0
    float xp[4];
    {
        const size_t base0 = ((size_t)b_0 * Lsz) * Gsz + j0 + jj_0;
        xp[0] = __ldg(g_xproj + base0);
        xp[1] = __ldg(g_xproj + base0 + 1024);
        xp[2] = __ldg(g_xproj + base0 + 2048);
        xp[3] = __ldg(g_xproj + base0 + 3072);
    }

    for (int t = 0; t < Lsz; ++t) {
        const __nv_bfloat16* hh = &g_hhi3[t % 3][0];
        const __nv_bfloat16* hl = &g_hlo3[t % 3][0];
        const unsigned need = (unsigned)t * 16;

        float acc[4][4];
        #pragma unroll
        for (int i = 0; i < 4; ++i)
            #pragma unroll
            for (int k = 0; k < 4; ++k) acc[i][k] = 0.0f;

        // A-fragment loader: k-tile kt (0..15) -> k = (kt>>1)*128 + kseg*32 + (kt&1)*16
        const size_t o0 = (size_t)row0 * Hsz + kseg * 32 + 2 * tg;
        const size_t o1 = (size_t)row1 * Hsz + kseg * 32 + 2 * tg;
        auto loadA = [&](int kt, unsigned* ah, unsigned* al) {
            const int ko = (kt >> 1) * 128 + (kt & 1) * 16;
            ah[0] = *(const unsigned*)(hh + o0 + ko);
            ah[1] = *(const unsigned*)(hh + o1 + ko);
            ah[2] = *(const unsigned*)(hh + o0 + ko + 8);
            ah[3] = *(const unsigned*)(hh + o1 + ko + 8);
            al[0] = *(const unsigned*)(hl + o0 + ko);
            al[1] = *(const unsigned*)(hl + o1 + ko);
            al[2] = *(const unsigned*)(hl + o0 + ko + 8);
            al[3] = *(const unsigned*)(hl + o1 + ko + 8);
        };

        unsigned ah[2][4], al[2][4];
        while (ld_acq(&g_rc[0]) < need) { }
        loadA(0, ah[0], al[0]);

        #pragma unroll
        for (int kt = 0; kt < NKT; ++kt) {
            const int cur = kt & 1;
            if (kt + 1 < NKT) {
                if (((kt + 1) & 1) == 0) {
                    const int nc = (kt + 1) >> 1;
                    while (ld_acq(&g_rc[nc]) < need) { }
                }
                loadA(kt + 1, ah[cur ^ 1], al[cur ^ 1]);
            }

            // B fragments: NG rows 0-15 and 16-31, k16 tile of this warp
            const int koffB = (kt >> 1) * 128 + kseg * 32 + (kt & 1) * 16 + bCol;
            unsigned bh0[4], bh1[4], bl0[4], bl1[4];
            ldsm_x4(bh0, whhi + bR0 * (Hsz + WPAD) + koffB);
            ldsm_x4(bh1, whhi + bR1 * (Hsz + WPAD) + koffB);
            ldsm_x4(bl0, whlo + bR0 * (Hsz + WPAD) + koffB);
            ldsm_x4(bl1, whlo + bR1 * (Hsz + WPAD) + koffB);

            mma16816(acc[0], ah[cur], bh0);
            mma16816(acc[0], ah[cur], bl0);
            mma16816(acc[0], al[cur], bh0);
            mma16816(acc[1], ah[cur], bh0 + 2);
            mma16816(acc[1], ah[cur], bl0 + 2);
            mma16816(acc[1], al[cur], bh0 + 2);
            mma16816(acc[2], ah[cur], bh1);
            mma16816(acc[2], ah[cur], bl1);
            mma16816(acc[2], al[cur], bh1);
            mma16816(acc[3], ah[cur], bh1 + 2);
            mma16816(acc[3], ah[cur], bl1 + 2);
            mma16816(acc[3], al[cur], bh1 + 2);
        }

        // partial gate pre-activations -> SMEM (per k-segment)
        float* gp = gates + kseg * (Bsz * NG);
        #pragma unroll
        for (int nt = 0; nt < 4; ++nt) {
            const int c = nt * 8 + 2 * tg;
            const int r = wm * 16 + g;
            gp[r * NG + c]           = acc[nt][0];
            gp[r * NG + c + 1]       = acc[nt][1];
            gp[(r + 8) * NG + c]     = acc[nt][2];
            gp[(r + 8) * NG + c + 1] = acc[nt][3];
        }
        __syncthreads();

        // LSTM cell: 512 items, one per thread; reduce 4 K-partials
        const int nb = (t + 1) % 3;
        {
            const int base = b_0 * NG + jj_0;
            float pf = xp[0], pi = xp[1], pg = xp[2], po = xp[3];
            #pragma unroll
            for (int s = 0; s < 4; ++s) {
                const float* gs = gates + s * (Bsz * NG) + base;
                pf += gs[0];
                pi += gs[8];
                pg += gs[16];
                po += gs[24];
            }
            const float f = sigmoidf_(pf);
            const float ii = sigmoidf_(pi);
            const float gg = tanhf_(pg);
            const float o = sigmoidf_(po);
            c_reg = f * c_reg + ii * gg;
            const float h = o * tanhf_(c_reg);
            out[((size_t)b_0 * Lsz + t) * Hsz + j0 + jj_0] = h;
            const __nv_bfloat16 hv = __float2bfloat16(h);
            g_hhi3[nb][b_0 * Hsz + j0 + jj_0] = hv;
            g_hlo3[nb][b_0 * Hsz + j0 + jj_0] = __float2bfloat16(h - __bfloat162float(hv));
        }

        // publish: this block finished step t for its region
        __threadfence();
        __syncthreads();
        if (tid == 0) atomicAdd(&g_rc[region], 1u);

        // prefetch xproj for next step
        if (t + 1 < Lsz) {
            const size_t base0 = ((size_t)b_0 * Lsz + (t + 1)) * Gsz + j0 + jj_0;
            xp[0] = __ldg(g_xproj + base0);
            xp[1] = __ldg(g_xproj + base0 + 1024);
            xp[2] = __ldg(g_xproj + base0 + 2048);
            xp[3] = __ldg(g_xproj + base0 + 3072);
        }
    }

    // finals
    {
        const float hv0 = out[((size_t)b_0 * Lsz + (Lsz - 1)) * Hsz + j0 + jj_0];
        out[OUTN + (size_t)b_0 * Hsz + j0 + jj_0] = hv0;
        out[OUTN + (size_t)Bsz * Hsz + (size_t)b_0 * Hsz + j0 + jj_0] = c_reg;
    }
}

// ---------------- launcher ----------------
extern "C" void kernel_launch(void* const* d_in, const int* in_sizes, int n_in,
                              void* d_out, int out_size) {
    const float* x = (const float*)d_in[0];
    const float* W = (const float*)d_in[1];
    const float* b = (const float*)d_in[2];
    float* out = (float*)d_out;

    split_x_kernel<<<2048, 256>>>(x);
    split_w_kernel<<<1024, 256>>>(W);
    init_kernel<<<256, 256>>>();

    dim3 g1(Gsz / P1_BN, ML / P1_BM);   // (32, 256)
    xproj_kernel<<<g1, 256>>>(b);

    cudaFuncSetAttribute(lstm_kernel, cudaFuncAttributeMaxDynamicSharedMemorySize,
                         (int)SMEM_P2);
    lstm_kernel<<<NBLK2, NTH2, SMEM_P2>>>(out);
}

// round 9
// speedup vs baseline: 1.4124x; 1.4124x over previous
#include <cuda_runtime.h>
#include <cuda_bf16.h>
#include <cuda_fp16.h>
#include <math.h>
#include <stdint.h>

#define Bsz 64
#define Lsz 512
#define DIN 1024
#define Hsz 1024
#define Gsz 4096
#define ML (Bsz*Lsz)            // 32768
#define OUTN ((size_t)Bsz*Lsz*Hsz) // 33554432

// ---------------- scratch (static device allocations) ----------------
__device__ float g_xproj[(size_t)ML*Gsz];                 // 512 MB
__device__ __nv_bfloat16 g_xhi[(size_t)ML*DIN];
__device__ __nv_bfloat16 g_xlo[(size_t)ML*DIN];
__device__ __nv_bfloat16 g_wxhi[(size_t)Gsz*DIN];
__device__ __nv_bfloat16 g_wxlo[(size_t)Gsz*DIN];
__device__ __half g_whhi_h[(size_t)Gsz*Hsz];   // Wh fp16 hi
__device__ __half g_whlo_h[(size_t)Gsz*Hsz];   // (Wh - hi) * 2048 in fp16
__device__ __half g_hh3[3][Bsz*Hsz];           // h, fp16, triple-buffered
__device__ unsigned g_rc[8];    // per-K-region step counters

// ---------------- helpers ----------------
__device__ __forceinline__ void mma16816(float* c, const unsigned* a, const unsigned* b) {
    asm volatile(
        "mma.sync.aligned.m16n8k16.row.col.f32.bf16.bf16.f32 "
        "{%0,%1,%2,%3}, {%4,%5,%6,%7}, {%8,%9}, {%0,%1,%2,%3};\n"
        : "+f"(c[0]), "+f"(c[1]), "+f"(c[2]), "+f"(c[3])
        : "r"(a[0]), "r"(a[1]), "r"(a[2]), "r"(a[3]), "r"(b[0]), "r"(b[1]));
}
__device__ __forceinline__ void mma16816h(float* c, const unsigned* a, const unsigned* b) {
    asm volatile(
        "mma.sync.aligned.m16n8k16.row.col.f32.f16.f16.f32 "
        "{%0,%1,%2,%3}, {%4,%5,%6,%7}, {%8,%9}, {%0,%1,%2,%3};\n"
        : "+f"(c[0]), "+f"(c[1]), "+f"(c[2]), "+f"(c[3])
        : "r"(a[0]), "r"(a[1]), "r"(a[2]), "r"(a[3]), "r"(b[0]), "r"(b[1]));
}

__device__ __forceinline__ void ldsm_x4(unsigned* r, const void* p) {
    unsigned a = (unsigned)__cvta_generic_to_shared(p);
    asm volatile("ldmatrix.sync.aligned.m8n8.x4.shared.b16 {%0,%1,%2,%3}, [%4];\n"
        : "=r"(r[0]), "=r"(r[1]), "=r"(r[2]), "=r"(r[3]) : "r"(a));
}

__device__ __forceinline__ void cp16(void* dst, const void* src) {
    unsigned d = (unsigned)__cvta_generic_to_shared(dst);
    asm volatile("cp.async.cg.shared.global [%0], [%1], 16;\n" :: "r"(d), "l"(src));
}
__device__ __forceinline__ void cp_commit() { asm volatile("cp.async.commit_group;\n"); }
__device__ __forceinline__ void cp_wait1()  { asm volatile("cp.async.wait_group 1;\n"); }
__device__ __forceinline__ void cp_wait0()  { asm volatile("cp.async.wait_group 0;\n"); }

__device__ __forceinline__ float sigmoidf_(float x) {
    return __fdividef(1.0f, 1.0f + __expf(-x));
}
__device__ __forceinline__ float tanhf_(float x) {
    return __fdividef(2.0f, 1.0f + __expf(-2.0f * x)) - 1.0f;
}

// ---------------- split kernels ----------------
__global__ void split_x_kernel(const float* __restrict__ x) {
    size_t stride = (size_t)gridDim.x * blockDim.x;
    for (size_t i = (size_t)blockIdx.x * blockDim.x + threadIdx.x;
         i < (size_t)ML * DIN; i += stride) {
        float v = x[i];
        __nv_bfloat16 hi = __float2bfloat16(v);
        g_xhi[i] = hi;
        g_xlo[i] = __float2bfloat16(v - __bfloat162float(hi));
    }
}

__global__ void split_w_kernel(const float* __restrict__ W) {
    size_t stride = (size_t)gridDim.x * blockDim.x;
    for (size_t i = (size_t)blockIdx.x * blockDim.x + threadIdx.x;
         i < (size_t)Gsz * (Hsz + DIN); i += stride) {
        int r = (int)(i >> 11);
        int c = (int)(i & 2047);
        float v = W[i];
        size_t d = (size_t)r * 1024 + (c & 1023);
        if (c < 1024) {
            // Wh in fp16: hi + 2048-scaled residual (keeps lo out of subnormals)
            __half hi = __float2half(v);
            g_whhi_h[d] = hi;
            g_whlo_h[d] = __float2half((v - __half2float(hi)) * 2048.0f);
        } else {
            __nv_bfloat16 hi = __float2bfloat16(v);
            g_wxhi[d] = hi;
            g_wxlo[d] = __float2bfloat16(v - __bfloat162float(hi));
        }
    }
}

__global__ void init_kernel() {
    int i = blockIdx.x * blockDim.x + threadIdx.x;
    if (i < 8) g_rc[i] = 0;
    if (i < Bsz * Hsz) g_hh3[0][i] = __float2half(0.0f);
}

// ---------------- phase 1: x_proj GEMM (R6 verbatim: reg-capped, 2 CTA/SM) ----------------
#define P1_BM 128
#define P1_BN 128
#define P1_BK 32
#define P1_ROW 40   // 32 + 8 pad

__global__ __launch_bounds__(256, 2) void xproj_kernel(const float* __restrict__ bias) {
    __shared__ __nv_bfloat16 As[2][2][P1_BM][P1_ROW];  // [buf][hi/lo]
    __shared__ __nv_bfloat16 Bs[2][2][P1_BN][P1_ROW];

    const int tid = threadIdx.x;
    const int wid = tid >> 5, lane = tid & 31;
    const int wm = wid & 3;
    const int wn = wid >> 2;
    const int m0 = blockIdx.y * P1_BM;
    const int n0 = blockIdx.x * P1_BN;

    float acc[2][8][4];
    #pragma unroll
    for (int i = 0; i < 2; ++i)
        #pragma unroll
        for (int j = 0; j < 8; ++j)
            #pragma unroll
            for (int k = 0; k < 4; ++k) acc[i][j][k] = 0.0f;

    const int lrow = tid >> 1;
    const int lcb  = (tid & 1) * 16;

    const __nv_bfloat16* srcAh = g_xhi  + (size_t)(m0 + lrow) * DIN + lcb;
    const __nv_bfloat16* srcAl = g_xlo  + (size_t)(m0 + lrow) * DIN + lcb;
    const __nv_bfloat16* srcBh = g_wxhi + (size_t)(n0 + lrow) * DIN + lcb;
    const __nv_bfloat16* srcBl = g_wxlo + (size_t)(n0 + lrow) * DIN + lcb;

    auto stage = [&](int buf, int k0) {
        cp16(&As[buf][0][lrow][lcb],     srcAh + k0);
        cp16(&As[buf][0][lrow][lcb + 8], srcAh + k0 + 8);
        cp16(&As[buf][1][lrow][lcb],     srcAl + k0);
        cp16(&As[buf][1][lrow][lcb + 8], srcAl + k0 + 8);
        cp16(&Bs[buf][0][lrow][lcb],     srcBh + k0);
        cp16(&Bs[buf][0][lrow][lcb + 8], srcBh + k0 + 8);
        cp16(&Bs[buf][1][lrow][lcb],     srcBl + k0);
        cp16(&Bs[buf][1][lrow][lcb + 8], srcBl + k0 + 8);
        cp_commit();
    };

    stage(0, 0);

    const int aRow = lane & 15;
    const int aCol = (lane >> 4) << 3;
    const int bRow = ((lane >> 4) << 3) + (lane & 7);
    const int bCol = ((lane >> 3) & 1) << 3;

    for (int k0 = 0; k0 < DIN; k0 += P1_BK) {
        const int buf = (k0 >> 5) & 1;
        const bool more = (k0 + P1_BK) < DIN;
        if (more) stage(buf ^ 1, k0 + P1_BK);
        if (more) cp_wait1(); else cp_wait0();
        __syncthreads();

        #pragma unroll
        for (int kk = 0; kk < 2; ++kk) {
            const int kb = kk * 16;
            unsigned ahi[2][4], alo[2][4];
            #pragma unroll
            for (int mt = 0; mt < 2; ++mt) {
                const int r0 = wm * 32 + mt * 16;
                ldsm_x4(ahi[mt], &As[buf][0][r0 + aRow][kb + aCol]);
                ldsm_x4(alo[mt], &As[buf][1][r0 + aRow][kb + aCol]);
            }
            #pragma unroll
            for (int p = 0; p < 4; ++p) {
                const int nb0 = wn * 64 + p * 16;
                unsigned bh[4], bl[4];
                ldsm_x4(bh, &Bs[buf][0][nb0 + bRow][kb + bCol]);
                ldsm_x4(bl, &Bs[buf][1][nb0 + bRow][kb + bCol]);
                #pragma unroll
                for (int mt = 0; mt < 2; ++mt) {
                    #pragma unroll
                    for (int q = 0; q < 2; ++q) {
                        float* a = acc[mt][p * 2 + q];
                        mma16816(a, ahi[mt], bh + 2 * q);
                        mma16816(a, ahi[mt], bl + 2 * q);
                        mma16816(a, alo[mt], bh + 2 * q);
                    }
                }
            }
        }
        __syncthreads();
    }

    // epilogue: +bias, store fp32
    const int g = lane >> 2, tg = lane & 3;
    #pragma unroll
    for (int nt = 0; nt < 8; ++nt) {
        const int c = n0 + wn * 64 + nt * 8 + 2 * tg;
        const float bv0 = bias[c], bv1 = bias[c + 1];
        #pragma unroll
        for (int mt = 0; mt < 2; ++mt) {
            const int r0 = m0 + wm * 32 + mt * 16 + g;
            float2 v0 = make_float2(acc[mt][nt][0] + bv0, acc[mt][nt][1] + bv1);
            float2 v1 = make_float2(acc[mt][nt][2] + bv0, acc[mt][nt][3] + bv1);
            *(float2*)&g_xproj[(size_t)r0 * Gsz + c]       = v0;
            *(float2*)&g_xproj[(size_t)(r0 + 8) * Gsz + c] = v1;
        }
    }
}

// ---------------- phase 2: persistent recurrent LSTM ----------------
// R6 skeleton: 512 threads, split-K over 2 warp groups, cp.async double-buffered
// h chunks. NEW: fp16 2-term math (Whi + 2048-scaled Wlo with separate acc),
// single fp16 h array, ONE combined region-wait per step (volatile v4 polls).
#define NBLK2 128
#define HPERB 8
#define NG 32
#define WPAD 8           // wh row length 1032
#define KC 128
#define HTPAD 8          // htile row length 136
#define NCHUNK (Hsz / KC)
#define NTH2 512

#define SM_WH   (NG * (Hsz + WPAD))
#define SM_HT   (Bsz * (KC + HTPAD))
#define SMEM_P2 ((size_t)(2*SM_WH + 2*SM_HT) * 2 + (size_t)(2*Bsz*NG) * 4)

__global__ __launch_bounds__(NTH2, 1) void lstm_kernel(float* __restrict__ out) {
    extern __shared__ char smem[];
    __half* whhi = (__half*)smem;                 // [NG][1032]
    __half* whlo = whhi + SM_WH;
    __half* ht[2];
    ht[0] = whlo + SM_WH;                          // [64][136]
    ht[1] = ht[0] + SM_HT;
    float* gates0 = (float*)(ht[1] + SM_HT);       // [64][32] partial K-low
    float* gates1 = gates0 + Bsz * NG;             // [64][32] partial K-high

    const int tid = threadIdx.x;
    const int wid = tid >> 5, lane = tid & 31;
    const int g = lane >> 2, tg = lane & 3;
    const int kgrp = wid >> 3;          // 0: k in [0,64), 1: k in [64,128) of chunk
    const int wl = wid & 7;
    const int wm = wl & 3;              // rows wm*16
    const int wn = wl >> 2;             // cols wn*16
    const int j0 = blockIdx.x * HPERB;
    const int region = blockIdx.x >> 4;

    const int aRow = lane & 15;
    const int aCol = (lane >> 4) << 3;
    const int bRow = wn * 16 + ((lane >> 4) << 3) + (lane & 7);
    const int bCol = ((lane >> 3) & 1) << 3;

    // Wh slice into SMEM (fp16 hi + scaled lo)
    for (int i = tid; i < NG * (Hsz / 8); i += NTH2) {
        const int n = i >> 7;
        const int cu = i & 127;
        const int q = n >> 3, jj = n & 7;
        const size_t src = (size_t)(q * 1024 + j0 + jj) * Hsz + cu * 8;
        *(uint4*)&whhi[n * (Hsz + WPAD) + cu * 8] = *(const uint4*)(g_whhi_h + src);
        *(uint4*)&whlo[n * (Hsz + WPAD) + cu * 8] = *(const uint4*)(g_whlo_h + src);
    }
    __syncthreads();

    // cell item: one per thread
    const int b_0 = tid >> 3, jj_0 = tid & 7;
    float c_reg = 0.0f;

    // prefetch xproj for step 0
    float xp[4];
    {
        const size_t base0 = ((size_t)b_0 * Lsz) * Gsz + j0 + jj_0;
        xp[0] = __ldg(g_xproj + base0);
        xp[1] = __ldg(g_xproj + base0 + 1024);
        xp[2] = __ldg(g_xproj + base0 + 2048);
        xp[3] = __ldg(g_xproj + base0 + 3072);
    }

    auto stage_h = [&](int buf, int kc, int hbuf) {
        const __half* sh = &g_hh3[hbuf][0];
        #pragma unroll
        for (int q = 0; q < 2; ++q) {
            const int i = tid + q * NTH2;           // 0..1023
            const int row = i >> 4;
            const int cu = i & 15;
            cp16(&ht[buf][row * (KC + HTPAD) + cu * 8],
                 sh + (size_t)row * Hsz + kc * KC + cu * 8);
        }
        cp_commit();
    };

    for (int t = 0; t < Lsz; ++t) {
        const int hbuf = t % 3;
        const unsigned need = (unsigned)t * 16;

        // ONE combined wait for all 8 regions (2 volatile v4 loads + acquire fence)
        {
            unsigned m;
            do {
                unsigned r0, r1, r2, r3, r4, r5, r6, r7;
                asm volatile("ld.volatile.global.v4.u32 {%0,%1,%2,%3}, [%4];"
                             : "=r"(r0), "=r"(r1), "=r"(r2), "=r"(r3) : "l"(g_rc));
                asm volatile("ld.volatile.global.v4.u32 {%0,%1,%2,%3}, [%4];"
                             : "=r"(r4), "=r"(r5), "=r"(r6), "=r"(r7) : "l"(g_rc + 4));
                m = umin(umin(umin(r0, r1), umin(r2, r3)),
                         umin(umin(r4, r5), umin(r6, r7)));
            } while (m < need);
            __threadfence();   // acquire for peer h writes
        }

        float acc[2][4], accL[2][4];
        #pragma unroll
        for (int i = 0; i < 2; ++i)
            #pragma unroll
            for (int k = 0; k < 4; ++k) { acc[i][k] = 0.0f; accL[i][k] = 0.0f; }

        stage_h(0, 0, hbuf);

        for (int kc = 0; kc < NCHUNK; ++kc) {
            const int buf = kc & 1;
            const bool more = (kc + 1) < NCHUNK;
            if (more) {
                stage_h(buf ^ 1, kc + 1, hbuf);
                cp_wait1();
            } else {
                cp_wait0();
            }
            __syncthreads();

            const __half* th = ht[buf];

            // split-K: this warp covers k in [kgrp*64, kgrp*64+64) of the chunk
            #pragma unroll
            for (int ks = 0; ks < 4; ++ks) {
                const int kb = kgrp * 64 + ks * 16;
                unsigned ah[4], bh[4], bl[4];
                ldsm_x4(ah, th + (wm * 16 + aRow) * (KC + HTPAD) + kb + aCol);
                const int koff = kc * KC + kb + bCol;
                ldsm_x4(bh, whhi + bRow * (Hsz + WPAD) + koff);
                ldsm_x4(bl, whlo + bRow * (Hsz + WPAD) + koff);
                mma16816h(acc[0],  ah, bh);
                mma16816h(accL[0], ah, bl);
                mma16816h(acc[1],  ah, bh + 2);
                mma16816h(accL[1], ah, bl + 2);
            }
            __syncthreads();
        }

        // partial gate pre-activations -> SMEM (combine scaled-lo here)
        const float LS = 1.0f / 2048.0f;
        float* gp = kgrp ? gates1 : gates0;
        #pragma unroll
        for (int nt = 0; nt < 2; ++nt) {
            const int c = wn * 16 + nt * 8 + 2 * tg;
            const int r = wm * 16 + g;
            gp[r * NG + c]           = acc[nt][0] + accL[nt][0] * LS;
            gp[r * NG + c + 1]       = acc[nt][1] + accL[nt][1] * LS;
            gp[(r + 8) * NG + c]     = acc[nt][2] + accL[nt][2] * LS;
            gp[(r + 8) * NG + c + 1] = acc[nt][3] + accL[nt][3] * LS;
        }
        __syncthreads();

        // LSTM cell: 512 items, one per thread; reduce the two K-partials
        const int nb = (t + 1) % 3;
        {
            const int base = b_0 * NG + jj_0;
            const float pf = gates0[base]      + gates1[base]      + xp[0];
            const float pi = gates0[base + 8]  + gates1[base + 8]  + xp[1];
            const float pg = gates0[base + 16] + gates1[base + 16] + xp[2];
            const float po = gates0[base + 24] + gates1[base + 24] + xp[3];
            const float f = sigmoidf_(pf);
            const float ii = sigmoidf_(pi);
            const float gg = tanhf_(pg);
            const float o = sigmoidf_(po);
            c_reg = f * c_reg + ii * gg;
            const float h = o * tanhf_(c_reg);
            out[((size_t)b_0 * Lsz + t) * Hsz + j0 + jj_0] = h;
            g_hh3[nb][b_0 * Hsz + j0 + jj_0] = __float2half(h);
        }

        // publish: this block finished step t for its region
        __threadfence();
        __syncthreads();
        if (tid == 0) atomicAdd(&g_rc[region], 1u);

        // prefetch xproj for next step
        if (t + 1 < Lsz) {
            const size_t base0 = ((size_t)b_0 * Lsz + (t + 1)) * Gsz + j0 + jj_0;
            xp[0] = __ldg(g_xproj + base0);
            xp[1] = __ldg(g_xproj + base0 + 1024);
            xp[2] = __ldg(g_xproj + base0 + 2048);
            xp[3] = __ldg(g_xproj + base0 + 3072);
        }
    }

    // finals
    {
        const float hv0 = out[((size_t)b_0 * Lsz + (Lsz - 1)) * Hsz + j0 + jj_0];
        out[OUTN + (size_t)b_0 * Hsz + j0 + jj_0] = hv0;
        out[OUTN + (size_t)Bsz * Hsz + (size_t)b_0 * Hsz + j0 + jj_0] = c_reg;
    }
}

// ---------------- launcher ----------------
extern "C" void kernel_launch(void* const* d_in, const int* in_sizes, int n_in,
                              void* d_out, int out_size) {
    const float* x = (const float*)d_in[0];
    const float* W = (const float*)d_in[1];
    const float* b = (const float*)d_in[2];
    float* out = (float*)d_out;

    split_x_kernel<<<2048, 256>>>(x);
    split_w_kernel<<<1024, 256>>>(W);
    init_kernel<<<256, 256>>>();

    dim3 g1(Gsz / P1_BN, ML / P1_BM);   // (32, 256)
    xproj_kernel<<<g1, 256>>>(b);

    cudaFuncSetAttribute(lstm_kernel, cudaFuncAttributeMaxDynamicSharedMemorySize,
                         (int)SMEM_P2);
    lstm_kernel<<<NBLK2, NTH2, SMEM_P2>>>(out);
}

// round 10
// speedup vs baseline: 1.5758x; 1.1157x over previous
#include <cuda_runtime.h>
#include <cuda_bf16.h>
#include <cuda_fp16.h>
#include <math.h>
#include <stdint.h>

#define Bsz 64
#define Lsz 512
#define DIN 1024
#define Hsz 1024
#define Gsz 4096
#define ML (Bsz*Lsz)            // 32768
#define OUTN ((size_t)Bsz*Lsz*Hsz) // 33554432

// ---------------- scratch (static device allocations) ----------------
__device__ float g_xproj[(size_t)ML*Gsz];                 // 512 MB
__device__ __half g_xh[(size_t)ML*DIN];        // x in fp16 (single plane)
__device__ __half g_wxhi_h[(size_t)Gsz*DIN];   // Wx fp16 hi
__device__ __half g_wxlo_h[(size_t)Gsz*DIN];   // Wx residual, fp16 (subnormal ok)
__device__ __half g_whhi_h[(size_t)Gsz*Hsz];   // Wh fp16 hi
__device__ __half g_whlo_h[(size_t)Gsz*Hsz];   // (Wh - hi) * 2048 in fp16
__device__ __half g_hh3[3][Bsz*Hsz];           // h, fp16, triple-buffered
__device__ unsigned g_rc[8];    // per-K-region step counters

// ---------------- helpers ----------------
__device__ __forceinline__ void mma16816h(float* c, const unsigned* a, const unsigned* b) {
    asm volatile(
        "mma.sync.aligned.m16n8k16.row.col.f32.f16.f16.f32 "
        "{%0,%1,%2,%3}, {%4,%5,%6,%7}, {%8,%9}, {%0,%1,%2,%3};\n"
        : "+f"(c[0]), "+f"(c[1]), "+f"(c[2]), "+f"(c[3])
        : "r"(a[0]), "r"(a[1]), "r"(a[2]), "r"(a[3]), "r"(b[0]), "r"(b[1]));
}

__device__ __forceinline__ void ldsm_x4(unsigned* r, const void* p) {
    unsigned a = (unsigned)__cvta_generic_to_shared(p);
    asm volatile("ldmatrix.sync.aligned.m8n8.x4.shared.b16 {%0,%1,%2,%3}, [%4];\n"
        : "=r"(r[0]), "=r"(r[1]), "=r"(r[2]), "=r"(r[3]) : "r"(a));
}

__device__ __forceinline__ void cp16(void* dst, const void* src) {
    unsigned d = (unsigned)__cvta_generic_to_shared(dst);
    asm volatile("cp.async.cg.shared.global [%0], [%1], 16;\n" :: "r"(d), "l"(src));
}
__device__ __forceinline__ void cp_commit() { asm volatile("cp.async.commit_group;\n"); }
__device__ __forceinline__ void cp_wait1()  { asm volatile("cp.async.wait_group 1;\n"); }
__device__ __forceinline__ void cp_wait0()  { asm volatile("cp.async.wait_group 0;\n"); }

__device__ __forceinline__ float sigmoidf_(float x) {
    return __fdividef(1.0f, 1.0f + __expf(-x));
}
__device__ __forceinline__ float tanhf_(float x) {
    return __fdividef(2.0f, 1.0f + __expf(-2.0f * x)) - 1.0f;
}

// ---------------- split kernels ----------------
__global__ void split_x_kernel(const float* __restrict__ x) {
    size_t stride = (size_t)gridDim.x * blockDim.x;
    for (size_t i = (size_t)blockIdx.x * blockDim.x + threadIdx.x;
         i < (size_t)ML * DIN; i += stride) {
        g_xh[i] = __float2half(x[i]);
    }
}

__global__ void split_w_kernel(const float* __restrict__ W) {
    size_t stride = (size_t)gridDim.x * blockDim.x;
    for (size_t i = (size_t)blockIdx.x * blockDim.x + threadIdx.x;
         i < (size_t)Gsz * (Hsz + DIN); i += stride) {
        int r = (int)(i >> 11);
        int c = (int)(i & 2047);
        float v = W[i];
        size_t d = (size_t)r * 1024 + (c & 1023);
        __half hi = __float2half(v);
        float res = v - __half2float(hi);
        if (c < 1024) {
            g_whhi_h[d] = hi;
            g_whlo_h[d] = __float2half(res * 2048.0f);  // scaled: normal range
        } else {
            g_wxhi_h[d] = hi;
            g_wxlo_h[d] = __float2half(res);            // unscaled: fp16 subnormal ok
        }
    }
}

__global__ void init_kernel() {
    int i = blockIdx.x * blockDim.x + threadIdx.x;
    if (i < 8) g_rc[i] = 0;
    if (i < Bsz * Hsz) g_hh3[0][i] = __float2half(0.0f);
}

// ---------------- phase 1: x_proj GEMM (fp16 2-term; R6 skeleton, reg-capped) ----------------
#define P1_BM 128
#define P1_BN 128
#define P1_BK 32
#define P1_ROW 40   // 32 + 8 pad

__global__ __launch_bounds__(256, 2) void xproj_kernel(const float* __restrict__ bias) {
    __shared__ __half As[2][P1_BM][P1_ROW];      // x, single plane
    __shared__ __half Bs[2][2][P1_BN][P1_ROW];   // Wx hi/lo

    const int tid = threadIdx.x;
    const int wid = tid >> 5, lane = tid & 31;
    const int wm = wid & 3;
    const int wn = wid >> 2;
    const int m0 = blockIdx.y * P1_BM;
    const int n0 = blockIdx.x * P1_BN;

    float acc[2][8][4];
    #pragma unroll
    for (int i = 0; i < 2; ++i)
        #pragma unroll
        for (int j = 0; j < 8; ++j)
            #pragma unroll
            for (int k = 0; k < 4; ++k) acc[i][j][k] = 0.0f;

    const int lrow = tid >> 1;
    const int lcb  = (tid & 1) * 16;

    const __half* srcA  = g_xh      + (size_t)(m0 + lrow) * DIN + lcb;
    const __half* srcBh = g_wxhi_h  + (size_t)(n0 + lrow) * DIN + lcb;
    const __half* srcBl = g_wxlo_h  + (size_t)(n0 + lrow) * DIN + lcb;

    auto stage = [&](int buf, int k0) {
        cp16(&As[buf][lrow][lcb],        srcA + k0);
        cp16(&As[buf][lrow][lcb + 8],    srcA + k0 + 8);
        cp16(&Bs[buf][0][lrow][lcb],     srcBh + k0);
        cp16(&Bs[buf][0][lrow][lcb + 8], srcBh + k0 + 8);
        cp16(&Bs[buf][1][lrow][lcb],     srcBl + k0);
        cp16(&Bs[buf][1][lrow][lcb + 8], srcBl + k0 + 8);
        cp_commit();
    };

    stage(0, 0);

    const int aRow = lane & 15;
    const int aCol = (lane >> 4) << 3;
    const int bRow = ((lane >> 4) << 3) + (lane & 7);
    const int bCol = ((lane >> 3) & 1) << 3;

    for (int k0 = 0; k0 < DIN; k0 += P1_BK) {
        const int buf = (k0 >> 5) & 1;
        const bool more = (k0 + P1_BK) < DIN;
        if (more) stage(buf ^ 1, k0 + P1_BK);
        if (more) cp_wait1(); else cp_wait0();
        __syncthreads();

        #pragma unroll
        for (int kk = 0; kk < 2; ++kk) {
            const int kb = kk * 16;
            unsigned a[2][4];
            #pragma unroll
            for (int mt = 0; mt < 2; ++mt) {
                const int r0 = wm * 32 + mt * 16;
                ldsm_x4(a[mt], &As[buf][r0 + aRow][kb + aCol]);
            }
            #pragma unroll
            for (int p = 0; p < 4; ++p) {
                const int nb0 = wn * 64 + p * 16;
                unsigned bh[4], bl[4];
                ldsm_x4(bh, &Bs[buf][0][nb0 + bRow][kb + bCol]);
                ldsm_x4(bl, &Bs[buf][1][nb0 + bRow][kb + bCol]);
                #pragma unroll
                for (int mt = 0; mt < 2; ++mt) {
                    #pragma unroll
                    for (int q = 0; q < 2; ++q) {
                        float* ac = acc[mt][p * 2 + q];
                        mma16816h(ac, a[mt], bh + 2 * q);
                        mma16816h(ac, a[mt], bl + 2 * q);
                    }
                }
            }
        }
        __syncthreads();
    }

    // epilogue: +bias, store fp32
    const int g = lane >> 2, tg = lane & 3;
    #pragma unroll
    for (int nt = 0; nt < 8; ++nt) {
        const int c = n0 + wn * 64 + nt * 8 + 2 * tg;
        const float bv0 = bias[c], bv1 = bias[c + 1];
        #pragma unroll
        for (int mt = 0; mt < 2; ++mt) {
            const int r0 = m0 + wm * 32 + mt * 16 + g;
            float2 v0 = make_float2(acc[mt][nt][0] + bv0, acc[mt][nt][1] + bv1);
            float2 v1 = make_float2(acc[mt][nt][2] + bv0, acc[mt][nt][3] + bv1);
            *(float2*)&g_xproj[(size_t)r0 * Gsz + c]       = v0;
            *(float2*)&g_xproj[(size_t)(r0 + 8) * Gsz + c] = v1;
        }
    }
}

// ---------------- phase 2: persistent recurrent LSTM (R9 + KC=256) ----------------
#define NBLK2 128
#define HPERB 8
#define NG 32
#define WPAD 8           // wh row length 1032
#define KC 256
#define HTPAD 8          // htile row length 264
#define NCHUNK (Hsz / KC)   // 4
#define NTH2 512

#define SM_WH   (NG * (Hsz + WPAD))
#define SM_HT   (Bsz * (KC + HTPAD))
#define SMEM_P2 ((size_t)(2*SM_WH + 2*SM_HT) * 2 + (size_t)(2*Bsz*NG) * 4)

__global__ __launch_bounds__(NTH2, 1) void lstm_kernel(float* __restrict__ out) {
    extern __shared__ char smem[];
    __half* whhi = (__half*)smem;                 // [NG][1032]
    __half* whlo = whhi + SM_WH;
    __half* ht[2];
    ht[0] = whlo + SM_WH;                          // [64][264]
    ht[1] = ht[0] + SM_HT;
    float* gates0 = (float*)(ht[1] + SM_HT);       // [64][32] partial K-low
    float* gates1 = gates0 + Bsz * NG;             // [64][32] partial K-high

    const int tid = threadIdx.x;
    const int wid = tid >> 5, lane = tid & 31;
    const int g = lane >> 2, tg = lane & 3;
    const int kgrp = wid >> 3;          // 0: k in [0,128), 1: k in [128,256) of chunk
    const int wl = wid & 7;
    const int wm = wl & 3;              // rows wm*16
    const int wn = wl >> 2;             // cols wn*16
    const int j0 = blockIdx.x * HPERB;
    const int region = blockIdx.x >> 4;

    const int aRow = lane & 15;
    const int aCol = (lane >> 4) << 3;
    const int bRow = wn * 16 + ((lane >> 4) << 3) + (lane & 7);
    const int bCol = ((lane >> 3) & 1) << 3;

    // Wh slice into SMEM (fp16 hi + scaled lo)
    for (int i = tid; i < NG * (Hsz / 8); i += NTH2) {
        const int n = i >> 7;
        const int cu = i & 127;
        const int q = n >> 3, jj = n & 7;
        const size_t src = (size_t)(q * 1024 + j0 + jj) * Hsz + cu * 8;
        *(uint4*)&whhi[n * (Hsz + WPAD) + cu * 8] = *(const uint4*)(g_whhi_h + src);
        *(uint4*)&whlo[n * (Hsz + WPAD) + cu * 8] = *(const uint4*)(g_whlo_h + src);
    }
    __syncthreads();

    // cell item: one per thread
    const int b_0 = tid >> 3, jj_0 = tid & 7;
    float c_reg = 0.0f;

    // prefetch xproj for step 0
    float xp[4];
    {
        const size_t base0 = ((size_t)b_0 * Lsz) * Gsz + j0 + jj_0;
        xp[0] = __ldg(g_xproj + base0);
        xp[1] = __ldg(g_xproj + base0 + 1024);
        xp[2] = __ldg(g_xproj + base0 + 2048);
        xp[3] = __ldg(g_xproj + base0 + 3072);
    }

    auto stage_h = [&](int buf, int kc, int hbuf) {
        const __half* sh = &g_hh3[hbuf][0];
        #pragma unroll
        for (int q = 0; q < 4; ++q) {
            const int i = tid + q * NTH2;           // 0..2047
            const int row = i >> 5;                 // 32 16B-chunks per row
            const int cu = i & 31;
            cp16(&ht[buf][row * (KC + HTPAD) + cu * 8],
                 sh + (size_t)row * Hsz + kc * KC + cu * 8);
        }
        cp_commit();
    };

    for (int t = 0; t < Lsz; ++t) {
        const int hbuf = t % 3;
        const unsigned need = (unsigned)t * 16;

        // ONE combined wait for all 8 regions (2 volatile v4 loads + acquire fence)
        {
            unsigned m;
            do {
                unsigned r0, r1, r2, r3, r4, r5, r6, r7;
                asm volatile("ld.volatile.global.v4.u32 {%0,%1,%2,%3}, [%4];"
                             : "=r"(r0), "=r"(r1), "=r"(r2), "=r"(r3) : "l"(g_rc));
                asm volatile("ld.volatile.global.v4.u32 {%0,%1,%2,%3}, [%4];"
                             : "=r"(r4), "=r"(r5), "=r"(r6), "=r"(r7) : "l"(g_rc + 4));
                m = umin(umin(umin(r0, r1), umin(r2, r3)),
                         umin(umin(r4, r5), umin(r6, r7)));
            } while (m < need);
            __threadfence();   // acquire for peer h writes
        }

        float acc[2][4], accL[2][4];
        #pragma unroll
        for (int i = 0; i < 2; ++i)
            #pragma unroll
            for (int k = 0; k < 4; ++k) { acc[i][k] = 0.0f; accL[i][k] = 0.0f; }

        stage_h(0, 0, hbuf);

        for (int kc = 0; kc < NCHUNK; ++kc) {
            const int buf = kc & 1;
            const bool more = (kc + 1) < NCHUNK;
            if (more) {
                stage_h(buf ^ 1, kc + 1, hbuf);
                cp_wait1();
            } else {
                cp_wait0();
            }
            __syncthreads();

            const __half* th = ht[buf];

            // split-K: this warp covers k in [kgrp*128, kgrp*128+128) of the chunk
            #pragma unroll
            for (int ks = 0; ks < 8; ++ks) {
                const int kb = kgrp * 128 + ks * 16;
                unsigned ah[4], bh[4], bl[4];
                ldsm_x4(ah, th + (wm * 16 + aRow) * (KC + HTPAD) + kb + aCol);
                const int koff = kc * KC + kb + bCol;
                ldsm_x4(bh, whhi + bRow * (Hsz + WPAD) + koff);
                ldsm_x4(bl, whlo + bRow * (Hsz + WPAD) + koff);
                mma16816h(acc[0],  ah, bh);
                mma16816h(accL[0], ah, bl);
                mma16816h(acc[1],  ah, bh + 2);
                mma16816h(accL[1], ah, bl + 2);
            }
            __syncthreads();
        }

        // partial gate pre-activations -> SMEM (combine scaled-lo here)
        const float LS = 1.0f / 2048.0f;
        float* gp = kgrp ? gates1 : gates0;
        #pragma unroll
        for (int nt = 0; nt < 2; ++nt) {
            const int c = wn * 16 + nt * 8 + 2 * tg;
            const int r = wm * 16 + g;
            gp[r * NG + c]           = acc[nt][0] + accL[nt][0] * LS;
            gp[r * NG + c + 1]       = acc[nt][1] + accL[nt][1] * LS;
            gp[(r + 8) * NG + c]     = acc[nt][2] + accL[nt][2] * LS;
            gp[(r + 8) * NG + c + 1] = acc[nt][3] + accL[nt][3] * LS;
        }
        __syncthreads();

        // LSTM cell: 512 items, one per thread; reduce the two K-partials
        const int nb = (t + 1) % 3;
        {
            const int base = b_0 * NG + jj_0;
            const float pf = gates0[base]      + gates1[base]      + xp[0];
            const float pi = gates0[base + 8]  + gates1[base + 8]  + xp[1];
            const float pg = gates0[base + 16] + gates1[base + 16] + xp[2];
            const float po = gates0[base + 24] + gates1[base + 24] + xp[3];
            const float f = sigmoidf_(pf);
            const float ii = sigmoidf_(pi);
            const float gg = tanhf_(pg);
            const float o = sigmoidf_(po);
            c_reg = f * c_reg + ii * gg;
            const float h = o * tanhf_(c_reg);
            out[((size_t)b_0 * Lsz + t) * Hsz + j0 + jj_0] = h;
            g_hh3[nb][b_0 * Hsz + j0 + jj_0] = __float2half(h);
        }

        // publish: this block finished step t for its region
        __threadfence();
        __syncthreads();
        if (tid == 0) atomicAdd(&g_rc[region], 1u);

        // prefetch xproj for next step
        if (t + 1 < Lsz) {
            const size_t base0 = ((size_t)b_0 * Lsz + (t + 1)) * Gsz + j0 + jj_0;
            xp[0] = __ldg(g_xproj + base0);
            xp[1] = __ldg(g_xproj + base0 + 1024);
            xp[2] = __ldg(g_xproj + base0 + 2048);
            xp[3] = __ldg(g_xproj + base0 + 3072);
        }
    }

    // finals
    {
        const float hv0 = out[((size_t)b_0 * Lsz + (Lsz - 1)) * Hsz + j0 + jj_0];
        out[OUTN + (size_t)b_0 * Hsz + j0 + jj_0] = hv0;
        out[OUTN + (size_t)Bsz * Hsz + (size_t)b_0 * Hsz + j0 + jj_0] = c_reg;
    }
}

// ---------------- launcher ----------------
extern "C" void kernel_launch(void* const* d_in, const int* in_sizes, int n_in,
                              void* d_out, int out_size) {
    const float* x = (const float*)d_in[0];
    const float* W = (const float*)d_in[1];
    const float* b = (const float*)d_in[2];
    float* out = (float*)d_out;

    split_x_kernel<<<2048, 256>>>(x);
    split_w_kernel<<<1024, 256>>>(W);
    init_kernel<<<256, 256>>>();

    dim3 g1(Gsz / P1_BN, ML / P1_BM);   // (32, 256)
    xproj_kernel<<<g1, 256>>>(b);

    cudaFuncSetAttribute(lstm_kernel, cudaFuncAttributeMaxDynamicSharedMemorySize,
                         (int)SMEM_P2);
    lstm_kernel<<<NBLK2, NTH2, SMEM_P2>>>(out);
}

// round 11
// speedup vs baseline: 1.7953x; 1.1393x over previous
#include <cuda_runtime.h>
#include <cuda_bf16.h>
#include <cuda_fp16.h>
#include <math.h>
#include <stdint.h>

#define Bsz 64
#define Lsz 512
#define DIN 1024
#define Hsz 1024
#define Gsz 4096
#define ML (Bsz*Lsz)            // 32768
#define OUTN ((size_t)Bsz*Lsz*Hsz) // 33554432

// ---------------- scratch (static device allocations) ----------------
__device__ float g_xproj[(size_t)ML*Gsz];                 // 512 MB
__device__ __half g_xh[(size_t)ML*DIN];        // x in fp16 (single plane)
__device__ __half g_wxhi_h[(size_t)Gsz*DIN];   // Wx fp16 (1-term; lo is HMMA-flushed anyway)
__device__ __half g_whhi_h[(size_t)Gsz*Hsz];   // fp16(512*Wh)
__device__ __half g_whlo_h[(size_t)Gsz*Hsz];   // fp16(512*Wh - hi)
__device__ __half g_hh3[3][Bsz*Hsz];           // h, fp16, triple-buffered
__device__ unsigned g_rc[8];    // per-K-region step counters

// ---------------- helpers ----------------
__device__ __forceinline__ void mma16816h(float* c, const unsigned* a, const unsigned* b) {
    asm volatile(
        "mma.sync.aligned.m16n8k16.row.col.f32.f16.f16.f32 "
        "{%0,%1,%2,%3}, {%4,%5,%6,%7}, {%8,%9}, {%0,%1,%2,%3};\n"
        : "+f"(c[0]), "+f"(c[1]), "+f"(c[2]), "+f"(c[3])
        : "r"(a[0]), "r"(a[1]), "r"(a[2]), "r"(a[3]), "r"(b[0]), "r"(b[1]));
}

__device__ __forceinline__ void ldsm_x4(unsigned* r, const void* p) {
    unsigned a = (unsigned)__cvta_generic_to_shared(p);
    asm volatile("ldmatrix.sync.aligned.m8n8.x4.shared.b16 {%0,%1,%2,%3}, [%4];\n"
        : "=r"(r[0]), "=r"(r[1]), "=r"(r[2]), "=r"(r[3]) : "r"(a));
}

__device__ __forceinline__ void cp16(void* dst, const void* src) {
    unsigned d = (unsigned)__cvta_generic_to_shared(dst);
    asm volatile("cp.async.cg.shared.global [%0], [%1], 16;\n" :: "r"(d), "l"(src));
}
__device__ __forceinline__ void cp_commit() { asm volatile("cp.async.commit_group;\n"); }
__device__ __forceinline__ void cp_wait1()  { asm volatile("cp.async.wait_group 1;\n"); }
__device__ __forceinline__ void cp_wait0()  { asm volatile("cp.async.wait_group 0;\n"); }

__device__ __forceinline__ float sigmoidf_(float x) {
    return __fdividef(1.0f, 1.0f + __expf(-x));
}
__device__ __forceinline__ float tanhf_(float x) {
    return __fdividef(2.0f, 1.0f + __expf(-2.0f * x)) - 1.0f;
}

// ---------------- split kernels ----------------
__global__ void split_x_kernel(const float* __restrict__ x) {
    size_t stride = (size_t)gridDim.x * blockDim.x;
    for (size_t i = (size_t)blockIdx.x * blockDim.x + threadIdx.x;
         i < (size_t)ML * DIN; i += stride) {
        g_xh[i] = __float2half(x[i]);
    }
}

__global__ void split_w_kernel(const float* __restrict__ W) {
    size_t stride = (size_t)gridDim.x * blockDim.x;
    for (size_t i = (size_t)blockIdx.x * blockDim.x + threadIdx.x;
         i < (size_t)Gsz * (Hsz + DIN); i += stride) {
        int r = (int)(i >> 11);
        int c = (int)(i & 2047);
        float v = W[i];
        size_t d = (size_t)r * 1024 + (c & 1023);
        if (c < 1024) {
            // Wh pre-scaled by 512: both terms share one accumulator; residual stays
            // in fp16 normal range (no HMMA denormal flush).
            float vs = v * 512.0f;
            __half hi = __float2half(vs);
            g_whhi_h[d] = hi;
            g_whlo_h[d] = __float2half(vs - __half2float(hi));
        } else {
            g_wxhi_h[d] = __float2half(v);   // 1-term (lo term is flushed by HMMA)
        }
    }
}

__global__ void init_kernel() {
    int i = blockIdx.x * blockDim.x + threadIdx.x;
    if (i < 8) g_rc[i] = 0;
    if (i < Bsz * Hsz) g_hh3[0][i] = __float2half(0.0f);
}

// ---------------- phase 1: x_proj GEMM (1-term fp16; R6 skeleton, reg-capped) ----------------
#define P1_BM 128
#define P1_BN 128
#define P1_BK 32
#define P1_ROW 40   // 32 + 8 pad

__global__ __launch_bounds__(256, 2) void xproj_kernel(const float* __restrict__ bias) {
    __shared__ __half As[2][P1_BM][P1_ROW];      // x
    __shared__ __half Bs[2][P1_BN][P1_ROW];      // Wx

    const int tid = threadIdx.x;
    const int wid = tid >> 5, lane = tid & 31;
    const int wm = wid & 3;
    const int wn = wid >> 2;
    const int m0 = blockIdx.y * P1_BM;
    const int n0 = blockIdx.x * P1_BN;

    float acc[2][8][4];
    #pragma unroll
    for (int i = 0; i < 2; ++i)
        #pragma unroll
        for (int j = 0; j < 8; ++j)
            #pragma unroll
            for (int k = 0; k < 4; ++k) acc[i][j][k] = 0.0f;

    const int lrow = tid >> 1;
    const int lcb  = (tid & 1) * 16;

    const __half* srcA  = g_xh     + (size_t)(m0 + lrow) * DIN + lcb;
    const __half* srcB  = g_wxhi_h + (size_t)(n0 + lrow) * DIN + lcb;

    auto stage = [&](int buf, int k0) {
        cp16(&As[buf][lrow][lcb],     srcA + k0);
        cp16(&As[buf][lrow][lcb + 8], srcA + k0 + 8);
        cp16(&Bs[buf][lrow][lcb],     srcB + k0);
        cp16(&Bs[buf][lrow][lcb + 8], srcB + k0 + 8);
        cp_commit();
    };

    stage(0, 0);

    const int aRow = lane & 15;
    const int aCol = (lane >> 4) << 3;
    const int bRow = ((lane >> 4) << 3) + (lane & 7);
    const int bCol = ((lane >> 3) & 1) << 3;

    for (int k0 = 0; k0 < DIN; k0 += P1_BK) {
        const int buf = (k0 >> 5) & 1;
        const bool more = (k0 + P1_BK) < DIN;
        if (more) stage(buf ^ 1, k0 + P1_BK);
        if (more) cp_wait1(); else cp_wait0();
        __syncthreads();

        #pragma unroll
        for (int kk = 0; kk < 2; ++kk) {
            const int kb = kk * 16;
            unsigned a[2][4];
            #pragma unroll
            for (int mt = 0; mt < 2; ++mt) {
                const int r0 = wm * 32 + mt * 16;
                ldsm_x4(a[mt], &As[buf][r0 + aRow][kb + aCol]);
            }
            #pragma unroll
            for (int p = 0; p < 4; ++p) {
                const int nb0 = wn * 64 + p * 16;
                unsigned bh[4];
                ldsm_x4(bh, &Bs[buf][nb0 + bRow][kb + bCol]);
                #pragma unroll
                for (int mt = 0; mt < 2; ++mt) {
                    #pragma unroll
                    for (int q = 0; q < 2; ++q) {
                        mma16816h(acc[mt][p * 2 + q], a[mt], bh + 2 * q);
                    }
                }
            }
        }
        __syncthreads();
    }

    // epilogue: +bias, store fp32
    const int g = lane >> 2, tg = lane & 3;
    #pragma unroll
    for (int nt = 0; nt < 8; ++nt) {
        const int c = n0 + wn * 64 + nt * 8 + 2 * tg;
        const float bv0 = bias[c], bv1 = bias[c + 1];
        #pragma unroll
        for (int mt = 0; mt < 2; ++mt) {
            const int r0 = m0 + wm * 32 + mt * 16 + g;
            float2 v0 = make_float2(acc[mt][nt][0] + bv0, acc[mt][nt][1] + bv1);
            float2 v1 = make_float2(acc[mt][nt][2] + bv0, acc[mt][nt][3] + bv1);
            *(float2*)&g_xproj[(size_t)r0 * Gsz + c]       = v0;
            *(float2*)&g_xproj[(size_t)(r0 + 8) * Gsz + c] = v1;
        }
    }
}

// ---------------- phase 2: persistent recurrent LSTM ----------------
// R10 skeleton + (a) 512-scaled Wh hi+lo into ONE accumulator, (b) single
// __syncthreads per chunk via stage-after-sync + cp_wait0.
#define NBLK2 128
#define HPERB 8
#define NG 32
#define WPAD 8           // wh row length 1032
#define KC 256
#define HTPAD 8          // htile row length 264
#define NCHUNK (Hsz / KC)   // 4
#define NTH2 512

#define SM_WH   (NG * (Hsz + WPAD))
#define SM_HT   (Bsz * (KC + HTPAD))
#define SMEM_P2 ((size_t)(2*SM_WH + 2*SM_HT) * 2 + (size_t)(2*Bsz*NG) * 4)

__global__ __launch_bounds__(NTH2, 1) void lstm_kernel(float* __restrict__ out) {
    extern __shared__ char smem[];
    __half* whhi = (__half*)smem;                 // [NG][1032]
    __half* whlo = whhi + SM_WH;
    __half* ht[2];
    ht[0] = whlo + SM_WH;                          // [64][264]
    ht[1] = ht[0] + SM_HT;
    float* gates0 = (float*)(ht[1] + SM_HT);       // [64][32] partial K-low
    float* gates1 = gates0 + Bsz * NG;             // [64][32] partial K-high

    const int tid = threadIdx.x;
    const int wid = tid >> 5, lane = tid & 31;
    const int g = lane >> 2, tg = lane & 3;
    const int kgrp = wid >> 3;          // 0: k in [0,128), 1: k in [128,256) of chunk
    const int wl = wid & 7;
    const int wm = wl & 3;              // rows wm*16
    const int wn = wl >> 2;             // cols wn*16
    const int j0 = blockIdx.x * HPERB;
    const int region = blockIdx.x >> 4;

    const int aRow = lane & 15;
    const int aCol = (lane >> 4) << 3;
    const int bRow = wn * 16 + ((lane >> 4) << 3) + (lane & 7);
    const int bCol = ((lane >> 3) & 1) << 3;

    // Wh slice into SMEM (512-scaled fp16 hi + lo)
    for (int i = tid; i < NG * (Hsz / 8); i += NTH2) {
        const int n = i >> 7;
        const int cu = i & 127;
        const int q = n >> 3, jj = n & 7;
        const size_t src = (size_t)(q * 1024 + j0 + jj) * Hsz + cu * 8;
        *(uint4*)&whhi[n * (Hsz + WPAD) + cu * 8] = *(const uint4*)(g_whhi_h + src);
        *(uint4*)&whlo[n * (Hsz + WPAD) + cu * 8] = *(const uint4*)(g_whlo_h + src);
    }
    __syncthreads();

    // cell item: one per thread
    const int b_0 = tid >> 3, jj_0 = tid & 7;
    float c_reg = 0.0f;

    // prefetch xproj for step 0
    float xp[4];
    {
        const size_t base0 = ((size_t)b_0 * Lsz) * Gsz + j0 + jj_0;
        xp[0] = __ldg(g_xproj + base0);
        xp[1] = __ldg(g_xproj + base0 + 1024);
        xp[2] = __ldg(g_xproj + base0 + 2048);
        xp[3] = __ldg(g_xproj + base0 + 3072);
    }

    auto stage_h = [&](int buf, int kc, int hbuf) {
        const __half* sh = &g_hh3[hbuf][0];
        #pragma unroll
        for (int q = 0; q < 4; ++q) {
            const int i = tid + q * NTH2;           // 0..2047
            const int row = i >> 5;                 // 32 16B-chunks per row
            const int cu = i & 31;
            cp16(&ht[buf][row * (KC + HTPAD) + cu * 8],
                 sh + (size_t)row * Hsz + kc * KC + cu * 8);
        }
        cp_commit();
    };

    for (int t = 0; t < Lsz; ++t) {
        const int hbuf = t % 3;
        const unsigned need = (unsigned)t * 16;

        // ONE combined wait for all 8 regions (2 volatile v4 loads + acquire fence)
        {
            unsigned m;
            do {
                unsigned r0, r1, r2, r3, r4, r5, r6, r7;
                asm volatile("ld.volatile.global.v4.u32 {%0,%1,%2,%3}, [%4];"
                             : "=r"(r0), "=r"(r1), "=r"(r2), "=r"(r3) : "l"(g_rc));
                asm volatile("ld.volatile.global.v4.u32 {%0,%1,%2,%3}, [%4];"
                             : "=r"(r4), "=r"(r5), "=r"(r6), "=r"(r7) : "l"(g_rc + 4));
                m = umin(umin(umin(r0, r1), umin(r2, r3)),
                         umin(umin(r4, r5), umin(r6, r7)));
            } while (m < need);
            __threadfence();   // acquire for peer h writes
        }

        float acc[2][4];
        #pragma unroll
        for (int i = 0; i < 2; ++i)
            #pragma unroll
            for (int k = 0; k < 4; ++k) acc[i][k] = 0.0f;

        stage_h(0, 0, hbuf);

        for (int kc = 0; kc < NCHUNK; ++kc) {
            const int buf = kc & 1;
            cp_wait0();
            __syncthreads();
            if (kc + 1 < NCHUNK) stage_h(buf ^ 1, kc + 1, hbuf);

            const __half* th = ht[buf];

            // split-K: this warp covers k in [kgrp*128, kgrp*128+128) of the chunk
            #pragma unroll
            for (int ks = 0; ks < 8; ++ks) {
                const int kb = kgrp * 128 + ks * 16;
                unsigned ah[4], bh[4], bl[4];
                ldsm_x4(ah, th + (wm * 16 + aRow) * (KC + HTPAD) + kb + aCol);
                const int koff = kc * KC + kb + bCol;
                ldsm_x4(bh, whhi + bRow * (Hsz + WPAD) + koff);
                ldsm_x4(bl, whlo + bRow * (Hsz + WPAD) + koff);
                mma16816h(acc[0], ah, bh);
                mma16816h(acc[0], ah, bl);
                mma16816h(acc[1], ah, bh + 2);
                mma16816h(acc[1], ah, bl + 2);
            }
        }
        __syncthreads();

        // partial gate pre-activations -> SMEM (un-scale 512 here)
        const float IS = 1.0f / 512.0f;
        float* gp = kgrp ? gates1 : gates0;
        #pragma unroll
        for (int nt = 0; nt < 2; ++nt) {
            const int c = wn * 16 + nt * 8 + 2 * tg;
            const int r = wm * 16 + g;
            gp[r * NG + c]           = acc[nt][0] * IS;
            gp[r * NG + c + 1]       = acc[nt][1] * IS;
            gp[(r + 8) * NG + c]     = acc[nt][2] * IS;
            gp[(r + 8) * NG + c + 1] = acc[nt][3] * IS;
        }
        __syncthreads();

        // LSTM cell: 512 items, one per thread; reduce the two K-partials
        const int nb = (t + 1) % 3;
        {
            const int base = b_0 * NG + jj_0;
            const float pf = gates0[base]      + gates1[base]      + xp[0];
            const float pi = gates0[base + 8]  + gates1[base + 8]  + xp[1];
            const float pg = gates0[base + 16] + gates1[base + 16] + xp[2];
            const float po = gates0[base + 24] + gates1[base + 24] + xp[3];
            const float f = sigmoidf_(pf);
            const float ii = sigmoidf_(pi);
            const float gg = tanhf_(pg);
            const float o = sigmoidf_(po);
            c_reg = f * c_reg + ii * gg;
            const float h = o * tanhf_(c_reg);
            out[((size_t)b_0 * Lsz + t) * Hsz + j0 + jj_0] = h;
            g_hh3[nb][b_0 * Hsz + j0 + jj_0] = __float2half(h);
        }

        // publish: this block finished step t for its region
        __threadfence();
        __syncthreads();
        if (tid == 0) atomicAdd(&g_rc[region], 1u);

        // prefetch xproj for next step
        if (t + 1 < Lsz) {
            const size_t base0 = ((size_t)b_0 * Lsz + (t + 1)) * Gsz + j0 + jj_0;
            xp[0] = __ldg(g_xproj + base0);
            xp[1] = __ldg(g_xproj + base0 + 1024);
            xp[2] = __ldg(g_xproj + base0 + 2048);
            xp[3] = __ldg(g_xproj + base0 + 3072);
        }
    }

    // finals
    {
        const float hv0 = out[((size_t)b_0 * Lsz + (Lsz - 1)) * Hsz + j0 + jj_0];
        out[OUTN + (size_t)b_0 * Hsz + j0 + jj_0] = hv0;
        out[OUTN + (size_t)Bsz * Hsz + (size_t)b_0 * Hsz + j0 + jj_0] = c_reg;
    }
}

// ---------------- launcher ----------------
extern "C" void kernel_launch(void* const* d_in, const int* in_sizes, int n_in,
                              void* d_out, int out_size) {
    const float* x = (const float*)d_in[0];
    const float* W = (const float*)d_in[1];
    const float* b = (const float*)d_in[2];
    float* out = (float*)d_out;

    split_x_kernel<<<2048, 256>>>(x);
    split_w_kernel<<<1024, 256>>>(W);
    init_kernel<<<256, 256>>>();

    dim3 g1(Gsz / P1_BN, ML / P1_BM);   // (32, 256)
    xproj_kernel<<<g1, 256>>>(b);

    cudaFuncSetAttribute(lstm_kernel, cudaFuncAttributeMaxDynamicSharedMemorySize,
                         (int)SMEM_P2);
    lstm_kernel<<<NBLK2, NTH2, SMEM_P2>>>(out);
}

// round 12
// speedup vs baseline: 2.0238x; 1.1273x over previous
#include <cuda_runtime.h>
#include <cuda_bf16.h>
#include <cuda_fp16.h>
#include <math.h>
#include <stdint.h>

#define Bsz 64
#define Lsz 512
#define DIN 1024
#define Hsz 1024
#define Gsz 4096
#define ML (Bsz*Lsz)            // 32768
#define OUTN ((size_t)Bsz*Lsz*Hsz) // 33554432

// ---------------- scratch (static device allocations) ----------------
__device__ float g_xproj[(size_t)ML*Gsz];                 // 512 MB
__device__ __half g_xh[(size_t)ML*DIN];        // x in fp16
__device__ __half g_wxhi_h[(size_t)Gsz*DIN];   // Wx fp16 (1-term)
__device__ __half g_whhi_h[(size_t)Gsz*Hsz];   // fp16(512*Wh) (1-term, kept normal-range)
__device__ __half g_hh3[3][Bsz*Hsz];           // h, fp16, triple-buffered
__device__ unsigned g_rc[8];    // per-K-region step counters

// ---------------- helpers ----------------
__device__ __forceinline__ void mma16816h(float* c, const unsigned* a, const unsigned* b) {
    asm volatile(
        "mma.sync.aligned.m16n8k16.row.col.f32.f16.f16.f32 "
        "{%0,%1,%2,%3}, {%4,%5,%6,%7}, {%8,%9}, {%0,%1,%2,%3};\n"
        : "+f"(c[0]), "+f"(c[1]), "+f"(c[2]), "+f"(c[3])
        : "r"(a[0]), "r"(a[1]), "r"(a[2]), "r"(a[3]), "r"(b[0]), "r"(b[1]));
}

__device__ __forceinline__ void ldsm_x4(unsigned* r, const void* p) {
    unsigned a = (unsigned)__cvta_generic_to_shared(p);
    asm volatile("ldmatrix.sync.aligned.m8n8.x4.shared.b16 {%0,%1,%2,%3}, [%4];\n"
        : "=r"(r[0]), "=r"(r[1]), "=r"(r[2]), "=r"(r[3]) : "r"(a));
}

__device__ __forceinline__ void cp16(void* dst, const void* src) {
    unsigned d = (unsigned)__cvta_generic_to_shared(dst);
    asm volatile("cp.async.cg.shared.global [%0], [%1], 16;\n" :: "r"(d), "l"(src));
}
__device__ __forceinline__ void cp_commit() { asm volatile("cp.async.commit_group;\n"); }
__device__ __forceinline__ void cp_wait1()  { asm volatile("cp.async.wait_group 1;\n"); }
__device__ __forceinline__ void cp_wait0()  { asm volatile("cp.async.wait_group 0;\n"); }

__device__ __forceinline__ float sigmoidf_(float x) {
    return __fdividef(1.0f, 1.0f + __expf(-x));
}
__device__ __forceinline__ float tanhf_(float x) {
    return __fdividef(2.0f, 1.0f + __expf(-2.0f * x)) - 1.0f;
}

// ---------------- split kernels ----------------
__global__ void split_x_kernel(const float* __restrict__ x) {
    size_t stride = (size_t)gridDim.x * blockDim.x;
    for (size_t i = (size_t)blockIdx.x * blockDim.x + threadIdx.x;
         i < (size_t)ML * DIN; i += stride) {
        g_xh[i] = __float2half(x[i]);
    }
}

__global__ void split_w_kernel(const float* __restrict__ W) {
    size_t stride = (size_t)gridDim.x * blockDim.x;
    for (size_t i = (size_t)blockIdx.x * blockDim.x + threadIdx.x;
         i < (size_t)Gsz * (Hsz + DIN); i += stride) {
        int r = (int)(i >> 11);
        int c = (int)(i & 2047);
        float v = W[i];
        size_t d = (size_t)r * 1024 + (c & 1023);
        if (c < 1024) {
            g_whhi_h[d] = __float2half(v * 512.0f);  // scaled: keeps tails normal-range
        } else {
            g_wxhi_h[d] = __float2half(v);
        }
    }
}

__global__ void init_kernel() {
    int i = blockIdx.x * blockDim.x + threadIdx.x;
    if (i < 8) g_rc[i] = 0;
    if (i < Bsz * Hsz) g_hh3[0][i] = __float2half(0.0f);
}

// ---------------- phase 1: x_proj GEMM (1-term fp16; R11 verbatim) ----------------
#define P1_BM 128
#define P1_BN 128
#define P1_BK 32
#define P1_ROW 40   // 32 + 8 pad

__global__ __launch_bounds__(256, 2) void xproj_kernel(const float* __restrict__ bias) {
    __shared__ __half As[2][P1_BM][P1_ROW];      // x
    __shared__ __half Bs[2][P1_BN][P1_ROW];      // Wx

    const int tid = threadIdx.x;
    const int wid = tid >> 5, lane = tid & 31;
    const int wm = wid & 3;
    const int wn = wid >> 2;
    const int m0 = blockIdx.y * P1_BM;
    const int n0 = blockIdx.x * P1_BN;

    float acc[2][8][4];
    #pragma unroll
    for (int i = 0; i < 2; ++i)
        #pragma unroll
        for (int j = 0; j < 8; ++j)
            #pragma unroll
            for (int k = 0; k < 4; ++k) acc[i][j][k] = 0.0f;

    const int lrow = tid >> 1;
    const int lcb  = (tid & 1) * 16;

    const __half* srcA  = g_xh     + (size_t)(m0 + lrow) * DIN + lcb;
    const __half* srcB  = g_wxhi_h + (size_t)(n0 + lrow) * DIN + lcb;

    auto stage = [&](int buf, int k0) {
        cp16(&As[buf][lrow][lcb],     srcA + k0);
        cp16(&As[buf][lrow][lcb + 8], srcA + k0 + 8);
        cp16(&Bs[buf][lrow][lcb],     srcB + k0);
        cp16(&Bs[buf][lrow][lcb + 8], srcB + k0 + 8);
        cp_commit();
    };

    stage(0, 0);

    const int aRow = lane & 15;
    const int aCol = (lane >> 4) << 3;
    const int bRow = ((lane >> 4) << 3) + (lane & 7);
    const int bCol = ((lane >> 3) & 1) << 3;

    for (int k0 = 0; k0 < DIN; k0 += P1_BK) {
        const int buf = (k0 >> 5) & 1;
        const bool more = (k0 + P1_BK) < DIN;
        if (more) stage(buf ^ 1, k0 + P1_BK);
        if (more) cp_wait1(); else cp_wait0();
        __syncthreads();

        #pragma unroll
        for (int kk = 0; kk < 2; ++kk) {
            const int kb = kk * 16;
            unsigned a[2][4];
            #pragma unroll
            for (int mt = 0; mt < 2; ++mt) {
                const int r0 = wm * 32 + mt * 16;
                ldsm_x4(a[mt], &As[buf][r0 + aRow][kb + aCol]);
            }
            #pragma unroll
            for (int p = 0; p < 4; ++p) {
                const int nb0 = wn * 64 + p * 16;
                unsigned bh[4];
                ldsm_x4(bh, &Bs[buf][nb0 + bRow][kb + bCol]);
                #pragma unroll
                for (int mt = 0; mt < 2; ++mt) {
                    #pragma unroll
                    for (int q = 0; q < 2; ++q) {
                        mma16816h(acc[mt][p * 2 + q], a[mt], bh + 2 * q);
                    }
                }
            }
        }
        __syncthreads();
    }

    // epilogue: +bias, store fp32
    const int g = lane >> 2, tg = lane & 3;
    #pragma unroll
    for (int nt = 0; nt < 8; ++nt) {
        const int c = n0 + wn * 64 + nt * 8 + 2 * tg;
        const float bv0 = bias[c], bv1 = bias[c + 1];
        #pragma unroll
        for (int mt = 0; mt < 2; ++mt) {
            const int r0 = m0 + wm * 32 + mt * 16 + g;
            float2 v0 = make_float2(acc[mt][nt][0] + bv0, acc[mt][nt][1] + bv1);
            float2 v1 = make_float2(acc[mt][nt][2] + bv0, acc[mt][nt][3] + bv1);
            *(float2*)&g_xproj[(size_t)r0 * Gsz + c]       = v0;
            *(float2*)&g_xproj[(size_t)(r0 + 8) * Gsz + c] = v1;
        }
    }
}

// ---------------- phase 2: persistent recurrent LSTM (R11 skeleton, Wh 1-term) ----------------
#define NBLK2 128
#define HPERB 8
#define NG 32
#define WPAD 8           // wh row length 1032
#define KC 256
#define HTPAD 8          // htile row length 264
#define NCHUNK (Hsz / KC)   // 4
#define NTH2 512

#define SM_WH   (NG * (Hsz + WPAD))
#define SM_HT   (Bsz * (KC + HTPAD))
#define SMEM_P2 ((size_t)(SM_WH + 2*SM_HT) * 2 + (size_t)(2*Bsz*NG) * 4)

__global__ __launch_bounds__(NTH2, 1) void lstm_kernel(float* __restrict__ out) {
    extern __shared__ char smem[];
    __half* whhi = (__half*)smem;                 // [NG][1032]
    __half* ht[2];
    ht[0] = whhi + SM_WH;                          // [64][264]
    ht[1] = ht[0] + SM_HT;
    float* gates0 = (float*)(ht[1] + SM_HT);       // [64][32] partial K-low
    float* gates1 = gates0 + Bsz * NG;             // [64][32] partial K-high

    const int tid = threadIdx.x;
    const int wid = tid >> 5, lane = tid & 31;
    const int g = lane >> 2, tg = lane & 3;
    const int kgrp = wid >> 3;          // 0: k in [0,128), 1: k in [128,256) of chunk
    const int wl = wid & 7;
    const int wm = wl & 3;              // rows wm*16
    const int wn = wl >> 2;             // cols wn*16
    const int j0 = blockIdx.x * HPERB;
    const int region = blockIdx.x >> 4;

    const int aRow = lane & 15;
    const int aCol = (lane >> 4) << 3;
    const int bRow = wn * 16 + ((lane >> 4) << 3) + (lane & 7);
    const int bCol = ((lane >> 3) & 1) << 3;

    // Wh slice into SMEM (512-scaled fp16, 1-term)
    for (int i = tid; i < NG * (Hsz / 8); i += NTH2) {
        const int n = i >> 7;
        const int cu = i & 127;
        const int q = n >> 3, jj = n & 7;
        const size_t src = (size_t)(q * 1024 + j0 + jj) * Hsz + cu * 8;
        *(uint4*)&whhi[n * (Hsz + WPAD) + cu * 8] = *(const uint4*)(g_whhi_h + src);
    }
    __syncthreads();

    // cell item: one per thread
    const int b_0 = tid >> 3, jj_0 = tid & 7;
    float c_reg = 0.0f;

    // prefetch xproj for step 0
    float xp[4];
    {
        const size_t base0 = ((size_t)b_0 * Lsz) * Gsz + j0 + jj_0;
        xp[0] = __ldg(g_xproj + base0);
        xp[1] = __ldg(g_xproj + base0 + 1024);
        xp[2] = __ldg(g_xproj + base0 + 2048);
        xp[3] = __ldg(g_xproj + base0 + 3072);
    }

    auto stage_h = [&](int buf, int kc, int hbuf) {
        const __half* sh = &g_hh3[hbuf][0];
        #pragma unroll
        for (int q = 0; q < 4; ++q) {
            const int i = tid + q * NTH2;           // 0..2047
            const int row = i >> 5;                 // 32 16B-chunks per row
            const int cu = i & 31;
            cp16(&ht[buf][row * (KC + HTPAD) + cu * 8],
                 sh + (size_t)row * Hsz + kc * KC + cu * 8);
        }
        cp_commit();
    };

    for (int t = 0; t < Lsz; ++t) {
        const int hbuf = t % 3;
        const unsigned need = (unsigned)t * 16;

        // ONE combined wait for all 8 regions (2 volatile v4 loads + acquire fence)
        {
            unsigned m;
            do {
                unsigned r0, r1, r2, r3, r4, r5, r6, r7;
                asm volatile("ld.volatile.global.v4.u32 {%0,%1,%2,%3}, [%4];"
                             : "=r"(r0), "=r"(r1), "=r"(r2), "=r"(r3) : "l"(g_rc));
                asm volatile("ld.volatile.global.v4.u32 {%0,%1,%2,%3}, [%4];"
                             : "=r"(r4), "=r"(r5), "=r"(r6), "=r"(r7) : "l"(g_rc + 4));
                m = umin(umin(umin(r0, r1), umin(r2, r3)),
                         umin(umin(r4, r5), umin(r6, r7)));
            } while (m < need);
            __threadfence();   // acquire for peer h writes
        }

        float acc[2][4];
        #pragma unroll
        for (int i = 0; i < 2; ++i)
            #pragma unroll
            for (int k = 0; k < 4; ++k) acc[i][k] = 0.0f;

        stage_h(0, 0, hbuf);

        for (int kc = 0; kc < NCHUNK; ++kc) {
            const int buf = kc & 1;
            cp_wait0();
            __syncthreads();
            if (kc + 1 < NCHUNK) stage_h(buf ^ 1, kc + 1, hbuf);

            const __half* th = ht[buf];

            // split-K: this warp covers k in [kgrp*128, kgrp*128+128) of the chunk
            #pragma unroll
            for (int ks = 0; ks < 8; ++ks) {
                const int kb = kgrp * 128 + ks * 16;
                unsigned ah[4], bh[4];
                ldsm_x4(ah, th + (wm * 16 + aRow) * (KC + HTPAD) + kb + aCol);
                const int koff = kc * KC + kb + bCol;
                ldsm_x4(bh, whhi + bRow * (Hsz + WPAD) + koff);
                mma16816h(acc[0], ah, bh);
                mma16816h(acc[1], ah, bh + 2);
            }
        }
        __syncthreads();

        // partial gate pre-activations -> SMEM (un-scale 512 here)
        const float IS = 1.0f / 512.0f;
        float* gp = kgrp ? gates1 : gates0;
        #pragma unroll
        for (int nt = 0; nt < 2; ++nt) {
            const int c = wn * 16 + nt * 8 + 2 * tg;
            const int r = wm * 16 + g;
            gp[r * NG + c]           = acc[nt][0] * IS;
            gp[r * NG + c + 1]       = acc[nt][1] * IS;
            gp[(r + 8) * NG + c]     = acc[nt][2] * IS;
            gp[(r + 8) * NG + c + 1] = acc[nt][3] * IS;
        }
        __syncthreads();

        // LSTM cell: 512 items, one per thread; reduce the two K-partials
        const int nb = (t + 1) % 3;
        {
            const int base = b_0 * NG + jj_0;
            const float pf = gates0[base]      + gates1[base]      + xp[0];
            const float pi = gates0[base + 8]  + gates1[base + 8]  + xp[1];
            const float pg = gates0[base + 16] + gates1[base + 16] + xp[2];
            const float po = gates0[base + 24] + gates1[base + 24] + xp[3];
            const float f = sigmoidf_(pf);
            const float ii = sigmoidf_(pi);
            const float gg = tanhf_(pg);
            const float o = sigmoidf_(po);
            c_reg = f * c_reg + ii * gg;
            const float h = o * tanhf_(c_reg);
            out[((size_t)b_0 * Lsz + t) * Hsz + j0 + jj_0] = h;
            g_hh3[nb][b_0 * Hsz + j0 + jj_0] = __float2half(h);
        }

        // publish: this block finished step t for its region
        __threadfence();
        __syncthreads();
        if (tid == 0) atomicAdd(&g_rc[region], 1u);

        // prefetch xproj for next step
        if (t + 1 < Lsz) {
            const size_t base0 = ((size_t)b_0 * Lsz + (t + 1)) * Gsz + j0 + jj_0;
            xp[0] = __ldg(g_xproj + base0);
            xp[1] = __ldg(g_xproj + base0 + 1024);
            xp[2] = __ldg(g_xproj + base0 + 2048);
            xp[3] = __ldg(g_xproj + base0 + 3072);
        }
    }

    // finals
    {
        const float hv0 = out[((size_t)b_0 * Lsz + (Lsz - 1)) * Hsz + j0 + jj_0];
        out[OUTN + (size_t)b_0 * Hsz + j0 + jj_0] = hv0;
        out[OUTN + (size_t)Bsz * Hsz + (size_t)b_0 * Hsz + j0 + jj_0] = c_reg;
    }
}

// ---------------- launcher ----------------
extern "C" void kernel_launch(void* const* d_in, const int* in_sizes, int n_in,
                              void* d_out, int out_size) {
    const float* x = (const float*)d_in[0];
    const float* W = (const float*)d_in[1];
    const float* b = (const float*)d_in[2];
    float* out = (float*)d_out;

    split_x_kernel<<<2048, 256>>>(x);
    split_w_kernel<<<1024, 256>>>(W);
    init_kernel<<<256, 256>>>();

    dim3 g1(Gsz / P1_BN, ML / P1_BM);   // (32, 256)
    xproj_kernel<<<g1, 256>>>(b);

    cudaFuncSetAttribute(lstm_kernel, cudaFuncAttributeMaxDynamicSharedMemorySize,
                         (int)SMEM_P2);
    lstm_kernel<<<NBLK2, NTH2, SMEM_P2>>>(out);
}